// round 1
// baseline (speedup 1.0000x reference)
#include <cuda_runtime.h>
#include <cuda_bf16.h>
#include <math.h>

// Problem constants
#define B_   512
#define C_   2048
#define HW_  64
#define CF_  512
#define J_   30
#define D_   15450          // J*(CF+3)
#define EPS_ 1e-5f

// Output layout (flattened tuple concat):
// root (512*6) @0, pose (512*126) @3072, shape (512*10) @67584, cam (512*3) @72704

// ---- scratch (static device globals; no allocation APIs) ----
__device__ float g_pooled[B_ * C_];                 // 4 MB
__device__ float g_F[(size_t)B_ * HW_ * CF_];       // 67 MB, layout [b][hw][cf]
__device__ float g_feat[(size_t)B_ * D_];           // 31.6 MB
__device__ float g_part[6 * B_ * 132];              // ksplit partials

// ---- packed f32x2 helpers (Blackwell sm_100+) ----
__device__ __forceinline__ unsigned long long pk2(float lo, float hi) {
    unsigned long long r;
    asm("mov.b64 %0, {%1, %2};" : "=l"(r) : "f"(lo), "f"(hi));
    return r;
}
__device__ __forceinline__ void fma2(unsigned long long& d, unsigned long long a,
                                     unsigned long long b) {
    asm("fma.rn.f32x2 %0, %1, %2, %0;" : "+l"(d) : "l"(a), "l"(b));
}
__device__ __forceinline__ float2 upk(unsigned long long v) {
    float2 r;
    asm("mov.b64 {%0, %1}, %2;" : "=f"(r.x), "=f"(r.y) : "l"(v));
    return r;
}

// ============================================================
// K0: global average pool over HxW -> pooled (B, C)
// ============================================================
__global__ void k_pool(const float* __restrict__ img) {
    int i = blockIdx.x * 256 + threadIdx.x;   // over B*C
    if (i >= B_ * C_) return;
    const float4* p = (const float4*)(img + (size_t)i * HW_);
    float s = 0.f;
#pragma unroll
    for (int t = 0; t < 16; t++) {
        float4 v = p[t];
        s += v.x + v.y + v.z + v.w;
    }
    g_pooled[i] = s * (1.0f / 64.0f);
}

// ============================================================
// K0b: shape/cam heads. one block per batch, 128 threads
// ============================================================
__global__ void k_heads(const float* __restrict__ sw, const float* __restrict__ sb,
                        const float* __restrict__ cw, const float* __restrict__ cb,
                        float* __restrict__ out) {
    int b = blockIdx.x;
    __shared__ float pr[C_];
    for (int i = threadIdx.x; i < C_; i += 128) pr[i] = g_pooled[b * C_ + i];
    __syncthreads();
    int w = threadIdx.x >> 5, l = threadIdx.x & 31;
    for (int o = w; o < 13; o += 4) {
        const float* wr = (o < 10) ? (sw + (size_t)o * C_) : (cw + (size_t)(o - 10) * C_);
        float s = 0.f;
        for (int k = l; k < C_; k += 32) s += pr[k] * wr[k];
#pragma unroll
        for (int off = 16; off; off >>= 1) s += __shfl_xor_sync(0xffffffffu, s, off);
        if (l == 0) {
            if (o < 10) out[67584 + b * 10 + o] = s + sb[o];
            else        out[72704 + b * 3 + (o - 10)] = s + cb[o - 10];
        }
    }
}

// ============================================================
// K1: 1x1 conv + BN(eval) + ReLU  (batched GEMM, fp32x2 packed FMA)
// block: one batch, 128 output channels (M) x 64 positions (N), K=2048
// grid (4, 512), 256 threads (tx=n-group 16x4, ty=m-group 16x8)
// output F[b][hw][cf]  (cf contiguous for the gather kernel)
// ============================================================
#define KC1 32
__global__ void __launch_bounds__(256) k_conv(
    const float* __restrict__ img, const float* __restrict__ W,
    const float* __restrict__ cbias, const float* __restrict__ gam,
    const float* __restrict__ bet, const float* __restrict__ mu,
    const float* __restrict__ var) {
    int b = blockIdx.y;
    int m0 = blockIdx.x * 128;
    __shared__ float Wt[KC1][132];   // [k][m], padded (row 528B, 16B aligned)
    __shared__ float Xt[KC1][68];    // [k][n], padded (row 272B, 16B aligned)
    int tid = threadIdx.x;
    int tx = tid & 15;    // n: 4 each
    int ty = tid >> 4;    // m: 8 each (4 pairs)
    const float* Xb = img + (size_t)b * C_ * HW_;

    unsigned long long acc[4][4];  // [m-pair][n]
#pragma unroll
    for (int i = 0; i < 4; i++)
#pragma unroll
        for (int j = 0; j < 4; j++) acc[i][j] = 0ull;

    for (int k0 = 0; k0 < C_; k0 += KC1) {
        // load W tile 128(m) x 32(k), coalesced along k, store transposed
#pragma unroll
        for (int i = 0; i < 16; i++) {
            int idx = tid + i * 256;
            int m = idx >> 5, k = idx & 31;
            Wt[k][m] = W[(size_t)(m0 + m) * C_ + k0 + k];
        }
        // load X tile 32(k) x 64(n), coalesced along n
#pragma unroll
        for (int i = 0; i < 8; i++) {
            int idx = tid + i * 256;
            int k = idx >> 6, n = idx & 63;
            Xt[k][n] = Xb[(size_t)(k0 + k) * HW_ + n];
        }
        __syncthreads();
#pragma unroll
        for (int k = 0; k < KC1; k++) {
            unsigned long long ap[4];
#pragma unroll
            for (int i = 0; i < 4; i++)
                ap[i] = *(const unsigned long long*)&Wt[k][ty * 8 + 2 * i];
            float4 bv = *(const float4*)&Xt[k][tx * 4];
            unsigned long long bd[4];
            bd[0] = pk2(bv.x, bv.x); bd[1] = pk2(bv.y, bv.y);
            bd[2] = pk2(bv.z, bv.z); bd[3] = pk2(bv.w, bv.w);
#pragma unroll
            for (int i = 0; i < 4; i++)
#pragma unroll
                for (int j = 0; j < 4; j++) fma2(acc[i][j], ap[i], bd[j]);
        }
        __syncthreads();
    }

    // epilogue: BN + ReLU, write F[b][hw][cf]
    float* Fb = g_F + (size_t)b * HW_ * CF_;
#pragma unroll
    for (int i = 0; i < 4; i++) {
        int m = m0 + ty * 8 + 2 * i;
        float rs0 = rsqrtf(var[m] + EPS_),     rs1 = rsqrtf(var[m + 1] + EPS_);
        float s0 = gam[m] * rs0,               s1 = gam[m + 1] * rs1;
        float bb0 = bet[m] + (cbias[m] - mu[m]) * s0;
        float bb1 = bet[m + 1] + (cbias[m + 1] - mu[m + 1]) * s1;
#pragma unroll
        for (int j = 0; j < 4; j++) {
            float2 v = upk(acc[i][j]);
            float r0 = fmaxf(v.x * s0 + bb0, 0.f);
            float r1 = fmaxf(v.y * s1 + bb1, 0.f);
            int n = tx * 4 + j;
            *(float2*)&Fb[(size_t)n * CF_ + m] = make_float2(r0, r1);
        }
    }
}

// ============================================================
// K2: bilinear gather -> feat (B, J*515)
// ============================================================
__global__ void k_gather(const float* __restrict__ coords) {
    int b = blockIdx.x;
    __shared__ int   sidx[J_][4];
    __shared__ float swt[J_][4];
    int tid = threadIdx.x;  // 256
    if (tid < J_) {
        float x = coords[(b * J_ + tid) * 3 + 0];
        float y = coords[(b * J_ + tid) * 3 + 1];
        float x0f = floorf(x), y0f = floorf(y);
        float wx1 = x - x0f, wy1 = y - y0f;
        float wx0 = 1.f - wx1, wy0 = 1.f - wy1;
        int x0 = (int)x0f, y0 = (int)y0f, x1 = x0 + 1, y1 = y0 + 1;
        int ys[4] = {y0, y0, y1, y1};
        int xs[4] = {x0, x1, x0, x1};
        float ws[4] = {wy0 * wx0, wy0 * wx1, wy1 * wx0, wy1 * wx1};
#pragma unroll
        for (int c = 0; c < 4; c++) {
            bool valid = (xs[c] >= 0) && (xs[c] < 8) && (ys[c] >= 0) && (ys[c] < 8);
            int yc = min(max(ys[c], 0), 7), xc = min(max(xs[c], 0), 7);
            sidx[tid][c] = yc * 8 + xc;
            swt[tid][c] = valid ? ws[c] : 0.f;
        }
    }
    __syncthreads();
    const float* Fb = g_F + (size_t)b * HW_ * CF_;
    float* fb = g_feat + (size_t)b * D_;
    for (int j = 0; j < J_; j++) {
        int i0 = sidx[j][0], i1 = sidx[j][1], i2 = sidx[j][2], i3 = sidx[j][3];
        float w0 = swt[j][0], w1 = swt[j][1], w2 = swt[j][2], w3 = swt[j][3];
        for (int cf = tid; cf < CF_; cf += 256) {
            float v = w0 * Fb[i0 * CF_ + cf] + w1 * Fb[i1 * CF_ + cf]
                    + w2 * Fb[i2 * CF_ + cf] + w3 * Fb[i3 * CF_ + cf];
            fb[j * 515 + cf] = v;
        }
    }
    for (int t = tid; t < J_ * 3; t += 256) {
        int j = t / 3, c = t % 3;
        fb[j * 515 + 512 + c] = coords[(b * J_ + j) * 3 + c];
    }
}

// ============================================================
// K3: big linear heads (root 6 + pose 126 = 132 outputs), K=15450
// grid (ntile=5, btile=8, ksplit=6). Block: 64 batches x 32 outputs.
// K split on joint boundaries: 5 joints * 515 = 2575 per split.
// ============================================================
#define KC3 32
__global__ void __launch_bounds__(256) k_bigmm(const float* __restrict__ rw,
                                               const float* __restrict__ pw) {
    int o0 = blockIdx.x * 32;
    int b0 = blockIdx.y * 64;
    int ks = blockIdx.z;
    int kbeg = ks * 2575, kend = kbeg + 2575;
    __shared__ float At[KC3][65];  // [k][m], stride 65 -> conflict-free stores
    __shared__ float Bt[KC3][33];  // [k][n]
    int tid = threadIdx.x;
    int tx = tid & 7;    // n: 4 each -> 32
    int ty = tid >> 3;   // m: 2 each -> 64
    float acc[2][4];
#pragma unroll
    for (int i = 0; i < 2; i++)
#pragma unroll
        for (int j = 0; j < 4; j++) acc[i][j] = 0.f;

    for (int kk = kbeg; kk < kend; kk += KC3) {
        // A tile: 64(m) x 32(k)
#pragma unroll
        for (int i = 0; i < 8; i++) {
            int idx = tid + i * 256;
            int m = idx >> 5, k = idx & 31;
            int kg = kk + k;
            At[k][m] = (kg < kend) ? g_feat[(size_t)(b0 + m) * D_ + kg] : 0.f;
        }
        // B tile: 32(n=output) x 32(k)
#pragma unroll
        for (int i = 0; i < 4; i++) {
            int idx = tid + i * 256;
            int n = idx >> 5, k = idx & 31;
            int o = o0 + n, kg = kk + k;
            float v = 0.f;
            if (o < 132 && kg < kend) {
                const float* wr = (o < 6) ? (rw + (size_t)o * D_)
                                          : (pw + (size_t)(o - 6) * D_);
                v = wr[kg];
            }
            Bt[k][n] = v;
        }
        __syncthreads();
#pragma unroll
        for (int k = 0; k < KC3; k++) {
            float a0 = At[k][ty * 2], a1 = At[k][ty * 2 + 1];
#pragma unroll
            for (int j = 0; j < 4; j++) {
                float bj = Bt[k][tx * 4 + j];
                acc[0][j] += a0 * bj;
                acc[1][j] += a1 * bj;
            }
        }
        __syncthreads();
    }
#pragma unroll
    for (int i = 0; i < 2; i++) {
        int b = b0 + ty * 2 + i;
#pragma unroll
        for (int j = 0; j < 4; j++) {
            int o = o0 + tx * 4 + j;
            if (o < 132)
                g_part[((size_t)ks * B_ + b) * 132 + o] = acc[i][j];
        }
    }
}

__global__ void k_reduce(const float* __restrict__ rb, const float* __restrict__ pb,
                         float* __restrict__ out) {
    int i = blockIdx.x * 256 + threadIdx.x;
    if (i >= B_ * 132) return;
    int b = i / 132, o = i % 132;
    float s = 0.f;
#pragma unroll
    for (int ks = 0; ks < 6; ks++) s += g_part[((size_t)ks * B_ + b) * 132 + o];
    if (o < 6) out[b * 6 + o] = s + rb[o];
    else       out[3072 + b * 126 + (o - 6)] = s + pb[o - 6];
}

// ============================================================
extern "C" void kernel_launch(void* const* d_in, const int* in_sizes, int n_in,
                              void* d_out, int out_size) {
    const float* img    = (const float*)d_in[0];
    const float* coords = (const float*)d_in[1];
    const float* conv_w = (const float*)d_in[2];
    const float* conv_b = (const float*)d_in[3];
    const float* gam    = (const float*)d_in[4];
    const float* bet    = (const float*)d_in[5];
    const float* mu     = (const float*)d_in[6];
    const float* var    = (const float*)d_in[7];
    const float* root_w = (const float*)d_in[8];
    const float* root_b = (const float*)d_in[9];
    const float* pose_w = (const float*)d_in[10];
    const float* pose_b = (const float*)d_in[11];
    const float* shp_w  = (const float*)d_in[12];
    const float* shp_b  = (const float*)d_in[13];
    const float* cam_w  = (const float*)d_in[14];
    const float* cam_b  = (const float*)d_in[15];
    float* out = (float*)d_out;

    k_pool<<<(B_ * C_ + 255) / 256, 256>>>(img);
    k_heads<<<B_, 128>>>(shp_w, shp_b, cam_w, cam_b, out);
    k_conv<<<dim3(4, B_), 256>>>(img, conv_w, conv_b, gam, bet, mu, var);
    k_gather<<<B_, 256>>>(coords);
    k_bigmm<<<dim3(5, 8, 6), 256>>>(root_w, pose_w);
    k_reduce<<<(B_ * 132 + 255) / 256, 256>>>(root_b, pose_b, out);
}

// round 2
// speedup vs baseline: 1.0008x; 1.0008x over previous
#include <cuda_runtime.h>
#include <cuda_bf16.h>
#include <math.h>

// Problem constants
#define B_   512
#define C_   2048
#define HW_  64
#define CF_  512
#define J_   30
#define D_   15450          // J*(CF+3)
#define EPS_ 1e-5f

// Output layout (flattened tuple concat):
// root (512*6) @0, pose (512*126) @3072, shape (512*10) @67584, cam (512*3) @72704

// ---- scratch (static device globals; no allocation APIs) ----
__device__ float g_pooled[B_ * C_];                 // 4 MB
__device__ float g_F[(size_t)B_ * HW_ * CF_];       // 67 MB, layout [b][hw][cf]
__device__ float g_feat[(size_t)B_ * D_];           // 31.6 MB
__device__ float g_part[6 * B_ * 132];              // ksplit partials

// ---- packed f32x2 helpers (Blackwell sm_100+) ----
__device__ __forceinline__ unsigned long long pk2(float lo, float hi) {
    unsigned long long r;
    asm("mov.b64 %0, {%1, %2};" : "=l"(r) : "f"(lo), "f"(hi));
    return r;
}
__device__ __forceinline__ void fma2(unsigned long long& d, unsigned long long a,
                                     unsigned long long b) {
    asm("fma.rn.f32x2 %0, %1, %2, %0;" : "+l"(d) : "l"(a), "l"(b));
}
__device__ __forceinline__ float2 upk(unsigned long long v) {
    float2 r;
    asm("mov.b64 {%0, %1}, %2;" : "=f"(r.x), "=f"(r.y) : "l"(v));
    return r;
}

// ============================================================
// K0: global average pool over HxW -> pooled (B, C)
// ============================================================
__global__ void k_pool(const float* __restrict__ img) {
    int i = blockIdx.x * 256 + threadIdx.x;   // over B*C
    if (i >= B_ * C_) return;
    const float4* p = (const float4*)(img + (size_t)i * HW_);
    float s = 0.f;
#pragma unroll
    for (int t = 0; t < 16; t++) {
        float4 v = p[t];
        s += v.x + v.y + v.z + v.w;
    }
    g_pooled[i] = s * (1.0f / 64.0f);
}

// ============================================================
// K0b: shape/cam heads. one block per batch, 128 threads
// ============================================================
__global__ void k_heads(const float* __restrict__ sw, const float* __restrict__ sb,
                        const float* __restrict__ cw, const float* __restrict__ cb,
                        float* __restrict__ out) {
    int b = blockIdx.x;
    __shared__ float pr[C_];
    for (int i = threadIdx.x; i < C_; i += 128) pr[i] = g_pooled[b * C_ + i];
    __syncthreads();
    int w = threadIdx.x >> 5, l = threadIdx.x & 31;
    for (int o = w; o < 13; o += 4) {
        const float* wr = (o < 10) ? (sw + (size_t)o * C_) : (cw + (size_t)(o - 10) * C_);
        float s = 0.f;
        for (int k = l; k < C_; k += 32) s += pr[k] * wr[k];
#pragma unroll
        for (int off = 16; off; off >>= 1) s += __shfl_xor_sync(0xffffffffu, s, off);
        if (l == 0) {
            if (o < 10) out[67584 + b * 10 + o] = s + sb[o];
            else        out[72704 + b * 3 + (o - 10)] = s + cb[o - 10];
        }
    }
}

// ============================================================
// K1: 1x1 conv + BN(eval) + ReLU  (batched GEMM, fp32x2 packed FMA)
// block: one batch, 128 output channels (M) x 64 positions (N), K=2048
// grid (4, 512), 256 threads (tx=n-group 16x4, ty=m-group 16x8)
// output F[b][hw][cf]  (cf contiguous for the gather kernel)
// ============================================================
#define KC1 32
__global__ void __launch_bounds__(256) k_conv(
    const float* __restrict__ img, const float* __restrict__ W,
    const float* __restrict__ cbias, const float* __restrict__ gam,
    const float* __restrict__ bet, const float* __restrict__ mu,
    const float* __restrict__ var) {
    int b = blockIdx.y;
    int m0 = blockIdx.x * 128;
    __shared__ float Wt[KC1][132];   // [k][m], padded (row 528B, 16B aligned)
    __shared__ float Xt[KC1][68];    // [k][n], padded (row 272B, 16B aligned)
    int tid = threadIdx.x;
    int tx = tid & 15;    // n: 4 each
    int ty = tid >> 4;    // m: 8 each (4 pairs)
    const float* Xb = img + (size_t)b * C_ * HW_;

    unsigned long long acc[4][4];  // [m-pair][n]
#pragma unroll
    for (int i = 0; i < 4; i++)
#pragma unroll
        for (int j = 0; j < 4; j++) acc[i][j] = 0ull;

    for (int k0 = 0; k0 < C_; k0 += KC1) {
        // load W tile 128(m) x 32(k), coalesced along k, store transposed
#pragma unroll
        for (int i = 0; i < 16; i++) {
            int idx = tid + i * 256;
            int m = idx >> 5, k = idx & 31;
            Wt[k][m] = W[(size_t)(m0 + m) * C_ + k0 + k];
        }
        // load X tile 32(k) x 64(n), coalesced along n
#pragma unroll
        for (int i = 0; i < 8; i++) {
            int idx = tid + i * 256;
            int k = idx >> 6, n = idx & 63;
            Xt[k][n] = Xb[(size_t)(k0 + k) * HW_ + n];
        }
        __syncthreads();
#pragma unroll
        for (int k = 0; k < KC1; k++) {
            unsigned long long ap[4];
#pragma unroll
            for (int i = 0; i < 4; i++)
                ap[i] = *(const unsigned long long*)&Wt[k][ty * 8 + 2 * i];
            float4 bv = *(const float4*)&Xt[k][tx * 4];
            unsigned long long bd[4];
            bd[0] = pk2(bv.x, bv.x); bd[1] = pk2(bv.y, bv.y);
            bd[2] = pk2(bv.z, bv.z); bd[3] = pk2(bv.w, bv.w);
#pragma unroll
            for (int i = 0; i < 4; i++)
#pragma unroll
                for (int j = 0; j < 4; j++) fma2(acc[i][j], ap[i], bd[j]);
        }
        __syncthreads();
    }

    // epilogue: BN + ReLU, write F[b][hw][cf]
    float* Fb = g_F + (size_t)b * HW_ * CF_;
#pragma unroll
    for (int i = 0; i < 4; i++) {
        int m = m0 + ty * 8 + 2 * i;
        float rs0 = rsqrtf(var[m] + EPS_),     rs1 = rsqrtf(var[m + 1] + EPS_);
        float s0 = gam[m] * rs0,               s1 = gam[m + 1] * rs1;
        float bb0 = bet[m] + (cbias[m] - mu[m]) * s0;
        float bb1 = bet[m + 1] + (cbias[m + 1] - mu[m + 1]) * s1;
#pragma unroll
        for (int j = 0; j < 4; j++) {
            float2 v = upk(acc[i][j]);
            float r0 = fmaxf(v.x * s0 + bb0, 0.f);
            float r1 = fmaxf(v.y * s1 + bb1, 0.f);
            int n = tx * 4 + j;
            *(float2*)&Fb[(size_t)n * CF_ + m] = make_float2(r0, r1);
        }
    }
}

// ============================================================
// K2: bilinear gather -> feat (B, J*515)
// ============================================================
__global__ void k_gather(const float* __restrict__ coords) {
    int b = blockIdx.x;
    __shared__ int   sidx[J_][4];
    __shared__ float swt[J_][4];
    int tid = threadIdx.x;  // 256
    if (tid < J_) {
        float x = coords[(b * J_ + tid) * 3 + 0];
        float y = coords[(b * J_ + tid) * 3 + 1];
        float x0f = floorf(x), y0f = floorf(y);
        float wx1 = x - x0f, wy1 = y - y0f;
        float wx0 = 1.f - wx1, wy0 = 1.f - wy1;
        int x0 = (int)x0f, y0 = (int)y0f, x1 = x0 + 1, y1 = y0 + 1;
        int ys[4] = {y0, y0, y1, y1};
        int xs[4] = {x0, x1, x0, x1};
        float ws[4] = {wy0 * wx0, wy0 * wx1, wy1 * wx0, wy1 * wx1};
#pragma unroll
        for (int c = 0; c < 4; c++) {
            bool valid = (xs[c] >= 0) && (xs[c] < 8) && (ys[c] >= 0) && (ys[c] < 8);
            int yc = min(max(ys[c], 0), 7), xc = min(max(xs[c], 0), 7);
            sidx[tid][c] = yc * 8 + xc;
            swt[tid][c] = valid ? ws[c] : 0.f;
        }
    }
    __syncthreads();
    const float* Fb = g_F + (size_t)b * HW_ * CF_;
    float* fb = g_feat + (size_t)b * D_;
    for (int j = 0; j < J_; j++) {
        int i0 = sidx[j][0], i1 = sidx[j][1], i2 = sidx[j][2], i3 = sidx[j][3];
        float w0 = swt[j][0], w1 = swt[j][1], w2 = swt[j][2], w3 = swt[j][3];
        for (int cf = tid; cf < CF_; cf += 256) {
            float v = w0 * Fb[i0 * CF_ + cf] + w1 * Fb[i1 * CF_ + cf]
                    + w2 * Fb[i2 * CF_ + cf] + w3 * Fb[i3 * CF_ + cf];
            fb[j * 515 + cf] = v;
        }
    }
    for (int t = tid; t < J_ * 3; t += 256) {
        int j = t / 3, c = t % 3;
        fb[j * 515 + 512 + c] = coords[(b * J_ + j) * 3 + c];
    }
}

// ============================================================
// K3: big linear heads (root 6 + pose 126 = 132 outputs), K=15450
// grid (ntile=5, btile=8, ksplit=6). Block: 64 batches x 32 outputs.
// K split on joint boundaries: 5 joints * 515 = 2575 per split.
// ============================================================
#define KC3 32
__global__ void __launch_bounds__(256) k_bigmm(const float* __restrict__ rw,
                                               const float* __restrict__ pw) {
    int o0 = blockIdx.x * 32;
    int b0 = blockIdx.y * 64;
    int ks = blockIdx.z;
    int kbeg = ks * 2575, kend = kbeg + 2575;
    __shared__ float At[KC3][65];  // [k][m], stride 65 -> conflict-free stores
    __shared__ float Bt[KC3][33];  // [k][n]
    int tid = threadIdx.x;
    int tx = tid & 7;    // n: 4 each -> 32
    int ty = tid >> 3;   // m: 2 each -> 64
    float acc[2][4];
#pragma unroll
    for (int i = 0; i < 2; i++)
#pragma unroll
        for (int j = 0; j < 4; j++) acc[i][j] = 0.f;

    for (int kk = kbeg; kk < kend; kk += KC3) {
        // A tile: 64(m) x 32(k)
#pragma unroll
        for (int i = 0; i < 8; i++) {
            int idx = tid + i * 256;
            int m = idx >> 5, k = idx & 31;
            int kg = kk + k;
            At[k][m] = (kg < kend) ? g_feat[(size_t)(b0 + m) * D_ + kg] : 0.f;
        }
        // B tile: 32(n=output) x 32(k)
#pragma unroll
        for (int i = 0; i < 4; i++) {
            int idx = tid + i * 256;
            int n = idx >> 5, k = idx & 31;
            int o = o0 + n, kg = kk + k;
            float v = 0.f;
            if (o < 132 && kg < kend) {
                const float* wr = (o < 6) ? (rw + (size_t)o * D_)
                                          : (pw + (size_t)(o - 6) * D_);
                v = wr[kg];
            }
            Bt[k][n] = v;
        }
        __syncthreads();
#pragma unroll
        for (int k = 0; k < KC3; k++) {
            float a0 = At[k][ty * 2], a1 = At[k][ty * 2 + 1];
#pragma unroll
            for (int j = 0; j < 4; j++) {
                float bj = Bt[k][tx * 4 + j];
                acc[0][j] += a0 * bj;
                acc[1][j] += a1 * bj;
            }
        }
        __syncthreads();
    }
#pragma unroll
    for (int i = 0; i < 2; i++) {
        int b = b0 + ty * 2 + i;
#pragma unroll
        for (int j = 0; j < 4; j++) {
            int o = o0 + tx * 4 + j;
            if (o < 132)
                g_part[((size_t)ks * B_ + b) * 132 + o] = acc[i][j];
        }
    }
}

__global__ void k_reduce(const float* __restrict__ rb, const float* __restrict__ pb,
                         float* __restrict__ out) {
    int i = blockIdx.x * 256 + threadIdx.x;
    if (i >= B_ * 132) return;
    int b = i / 132, o = i % 132;
    float s = 0.f;
#pragma unroll
    for (int ks = 0; ks < 6; ks++) s += g_part[((size_t)ks * B_ + b) * 132 + o];
    if (o < 6) out[b * 6 + o] = s + rb[o];
    else       out[3072 + b * 126 + (o - 6)] = s + pb[o - 6];
}

// ============================================================
extern "C" void kernel_launch(void* const* d_in, const int* in_sizes, int n_in,
                              void* d_out, int out_size) {
    const float* img    = (const float*)d_in[0];
    const float* coords = (const float*)d_in[1];
    const float* conv_w = (const float*)d_in[2];
    const float* conv_b = (const float*)d_in[3];
    const float* gam    = (const float*)d_in[4];
    const float* bet    = (const float*)d_in[5];
    const float* mu     = (const float*)d_in[6];
    const float* var    = (const float*)d_in[7];
    const float* root_w = (const float*)d_in[8];
    const float* root_b = (const float*)d_in[9];
    const float* pose_w = (const float*)d_in[10];
    const float* pose_b = (const float*)d_in[11];
    const float* shp_w  = (const float*)d_in[12];
    const float* shp_b  = (const float*)d_in[13];
    const float* cam_w  = (const float*)d_in[14];
    const float* cam_b  = (const float*)d_in[15];
    float* out = (float*)d_out;

    k_pool<<<(B_ * C_ + 255) / 256, 256>>>(img);
    k_heads<<<B_, 128>>>(shp_w, shp_b, cam_w, cam_b, out);
    k_conv<<<dim3(4, B_), 256>>>(img, conv_w, conv_b, gam, bet, mu, var);
    k_gather<<<B_, 256>>>(coords);
    k_bigmm<<<dim3(5, 8, 6), 256>>>(root_w, pose_w);
    k_reduce<<<(B_ * 132 + 255) / 256, 256>>>(root_b, pose_b, out);
}